// round 15
// baseline (speedup 1.0000x reference)
#include <cuda_runtime.h>
#include <cuda_fp16.h>
#include <math.h>
#include <stdint.h>

#define D_DIM 2048
#define N_TOK 4096

// ---------------- device scratch (allocation-free rule) ----------------
__device__ __align__(128) __half g_xT_hi[(size_t)D_DIM * N_TOK];
__device__ __align__(128) __half g_x_hi [(size_t)N_TOK * D_DIM];
__device__ __align__(128) __half g_wqT_hi[(size_t)D_DIM * D_DIM];
__device__ __align__(128) __half g_wkT_hi[(size_t)D_DIM * D_DIM];
__device__ __align__(128) __half g_wv_hi[(size_t)D_DIM * D_DIM];
__device__ __align__(128) __half g_g_hi [(size_t)D_DIM * D_DIM];
__device__ __align__(128) __half g_t1_hi[(size_t)D_DIM * D_DIM];
__device__ __align__(128) __half g_t2_hi[(size_t)D_DIM * D_DIM];
__device__ __align__(128) __half g_pT_hi[(size_t)D_DIM * D_DIM];
__device__ float g_part[48 * D_DIM];
__device__ float g_u[D_DIM], g_w1[D_DIM], g_w2[D_DIM];
__device__ float g_v1[D_DIM], g_v2[D_DIM], g_v3[D_DIM], g_r[D_DIM];
__device__ float g_t[N_TOK], g_y[D_DIM];
__device__ float g_sc[2];
// tile flags: [0,256) G, [256,512) T1, [512,768) T2, [768,1024) P
__device__ int g_flags[1024];
// vec-stage counters: 0:A 1:B 2:C 3:D 4:E 5:F
__device__ int g_vcnt[8];

// ---------------- helpers ----------------
__device__ __forceinline__ uint32_t s2u(const void* p) {
    uint32_t a;
    asm("{ .reg .u64 t; cvta.to.shared.u64 t, %1; cvt.u32.u64 %0, t; }" : "=r"(a) : "l"(p));
    return a;
}
__device__ __forceinline__ void cp16(uint32_t dst, const void* src) {
    asm volatile("cp.async.cg.shared.global [%0], [%1], 16;" :: "r"(dst), "l"(src) : "memory");
}
__device__ __forceinline__ void cp_commit() {
    asm volatile("cp.async.commit_group;" ::: "memory");
}
template<int N>
__device__ __forceinline__ void cp_wait() {
    asm volatile("cp.async.wait_group %0;" :: "n"(N) : "memory");
}
__device__ __forceinline__ void ldsm4(uint32_t* r, uint32_t addr) {
    asm volatile("ldmatrix.sync.aligned.m8n8.x4.shared.b16 {%0,%1,%2,%3}, [%4];"
                 : "=r"(r[0]), "=r"(r[1]), "=r"(r[2]), "=r"(r[3]) : "r"(addr));
}
__device__ __forceinline__ void mma16816(float* d, const uint32_t* a, uint32_t b0, uint32_t b1) {
    asm volatile(
        "mma.sync.aligned.m16n8k16.row.col.f32.f16.f16.f32 "
        "{%0,%1,%2,%3}, {%4,%5,%6,%7}, {%8,%9}, {%0,%1,%2,%3};"
        : "+f"(d[0]), "+f"(d[1]), "+f"(d[2]), "+f"(d[3])
        : "r"(a[0]), "r"(a[1]), "r"(a[2]), "r"(a[3]), "r"(b0), "r"(b1));
}
__device__ __forceinline__ void wait_kblk(volatile int* wA, volatile int* wB, int sB,
                                          int kb, int tid) {
    if (tid == 0) {
        if (wA) while (wA[kb] == 0) __nanosleep(128);
        while (wB[kb * sB] == 0) __nanosleep(128);
        __threadfence();
    }
    __syncthreads();
}
__device__ __forceinline__ void vwait(volatile int* cnt, int target) {
    if (threadIdx.x == 0) {
        while (*cnt < target) __nanosleep(256);
        __threadfence();
    }
    __syncthreads();
}
__device__ __forceinline__ void vdone(int* cnt) {
    __threadfence();
    __syncthreads();
    if (threadIdx.x == 0) atomicAdd(cnt, 1);
}

// ---------------- pure fp16 HMMA GEMM body (single pass, BK=64) ----------------
// Template MF = m-fragments per warp (4 -> 128-row tile, 2 -> 64-row tile).
// C[m,n] = alpha * sum_k Ah[m,k] * Bh[n,k]
// mode 0 NORM / 1 SYM / 2 TRANS+rank2 / 3 FINAL fp32
// wB != null => progressive waits per 128-wide K-block (every 2nd chunk).
#define STAGE_B 36864              // max stage (MF=4): (128+128) rows x 144 B
static const int SMEM_DYN = 2 * STAGE_B;

template<int MF>
__device__ __forceinline__ void gemm_body(
    const __half* __restrict__ Ah, const __half* __restrict__ Bh,
    __half* Ch, float* Cf,
    const float* cA, const float* cB, const float* cC, const float* cD,
    const float* biascol,
    int bm0, int bn0, int Mtot, int Ntot, int Kd, float alpha, int mode,
    volatile int* wA, volatile int* wB, int sB,
    char* dyn)
{
    const int AROWS = MF * 32;                 // A tile rows
    const int APL   = AROWS * 144;             // A plane bytes
    const int STG   = (AROWS + 128) * 144;     // stage bytes
    const int NT    = MF + 4;                  // 16B transfers per thread

    const uint32_t su = s2u(dyn);
    const int tid  = threadIdx.x;
    const int wid  = tid >> 5, lane = tid & 31;
    const int wm0  = (wid & 1) * (MF * 16);
    const int wn0  = (wid >> 1) * 32;

    // cp.async: (AROWS+128)*8 transfers / 256 threads = NT each (A then B, contiguous)
    const __half* gsrc[NT];
    uint32_t doff[NT];
    #pragma unroll
    for (int i = 0; i < NT; ++i) {
        int idx = i * 256 + tid;
        int rowg = idx >> 3;                   // 0 .. AROWS+127
        int seg  = idx & 7;
        bool isA = rowg < AROWS;
        const __half* base = isA ? Ah : Bh;
        int grow = isA ? (bm0 + rowg) : (bn0 + rowg - AROWS);
        gsrc[i] = base + (size_t)grow * Kd + seg * 8;
        doff[i] = (uint32_t)(rowg * 144 + seg * 16);
    }

    const int NC = Kd / 64;
    if (wB) wait_kblk(wA, wB, sB, 0, tid);
    #pragma unroll
    for (int i = 0; i < NT; ++i) cp16(su + doff[i], gsrc[i]);
    cp_commit();

    float acc[MF][4][4];
    #pragma unroll
    for (int im = 0; im < MF; ++im)
        #pragma unroll
        for (int in = 0; in < 4; ++in)
            #pragma unroll
            for (int j = 0; j < 4; ++j) acc[im][in][j] = 0.0f;

    const int a_rl = ((lane >> 3) & 1) * 8 + (lane & 7);
    const int a_ch = ((lane >> 4) & 1) * 16;
    const int b_rl = lane;

    for (int c = 0; c < NC; ++c) {
        cp_wait<0>();
        __syncthreads();
        if (c + 1 < NC) {
            if (wB && (((c + 1) & 1) == 0))
                wait_kblk(wA, wB, sB, (c + 1) >> 1, tid);
            const uint32_t sd = su + ((c + 1) & 1) * STG;
            const size_t koff = (size_t)(c + 1) * 64;
            #pragma unroll
            for (int i = 0; i < NT; ++i) cp16(sd + doff[i], gsrc[i] + koff);
            cp_commit();
        }
        const uint32_t sb = su + (c & 1) * STG;
        const uint32_t aBase = sb + (wm0 + a_rl) * 144 + a_ch;
        const uint32_t bBase = sb + (wn0 + b_rl) * 144 + APL;

        #pragma unroll
        for (int kk = 0; kk < 4; ++kk) {
            const uint32_t kO = kk * 32;
            uint32_t a[MF][4], b0[4], b1[4];
            ldsm4(b0, bBase + kO);
            ldsm4(b1, bBase + kO + 16);
            #pragma unroll
            for (int im = 0; im < MF; ++im)
                ldsm4(a[im], aBase + im * (16 * 144) + kO);
            #pragma unroll
            for (int im = 0; im < MF; ++im)
                #pragma unroll
                for (int in = 0; in < 4; ++in)
                    mma16816(acc[im][in], a[im], b0[in], b1[in]);
        }
    }

    // ---- epilogue ----
    const int mbase = bm0 + wm0 + (lane >> 2);
    const int nbase = bn0 + wn0 + (lane & 3) * 2;
    #pragma unroll
    for (int im = 0; im < MF; ++im) {
        #pragma unroll
        for (int in = 0; in < 4; ++in) {
            const float* d = acc[im][in];
            const int n0 = nbase + in * 8;
            if (mode == 3) {
                const int m0 = mbase + im * 16;
                float2 v0, v1;
                v0.x = d[0] * alpha + biascol[n0];
                v0.y = d[1] * alpha + biascol[n0 + 1];
                v1.x = d[2] * alpha + biascol[n0];
                v1.y = d[3] * alpha + biascol[n0 + 1];
                *(float2*)(Cf + (size_t)m0 * Ntot + n0)       = v0;
                *(float2*)(Cf + (size_t)(m0 + 8) * Ntot + n0) = v1;
            } else {
                #pragma unroll
                for (int j = 0; j < 4; ++j) {
                    const int m = mbase + im * 16 + (j >> 1) * 8;
                    const int n = n0 + (j & 1);
                    float v = d[j] * alpha;
                    if (mode == 2) v += cA[m] * cB[n] + cC[m] * cD[n];
                    __half h = __float2half(v);
                    if (mode == 0) {
                        Ch[(size_t)m * Ntot + n] = h;
                    } else if (mode == 1) {
                        Ch[(size_t)m * Ntot + n] = h;
                        Ch[(size_t)n * Ntot + m] = h;
                    } else {
                        Ch[(size_t)n * Mtot + m] = h;
                    }
                }
            }
        }
    }
}

__device__ __forceinline__ void set_flags(int f0, int f1) {
    __threadfence();
    __syncthreads();
    if (threadIdx.x == 0) {
        atomicExch(g_flags + f0, 1);
        if (f1 >= 0) atomicExch(g_flags + f1, 1);
    }
}

// ---------------- vec chain inside mega: idx in [0,1002) ----------------
__device__ void vec_work(int idx,
                         const float* x, const float* Wq, const float* bq,
                         const float* Wk, const float* bk,
                         const float* Wv, const float* bv, float sscale)
{
    const int tid = threadIdx.x;
    if (idx < 384) {
        int dblk = idx & 7, c = (idx >> 3) & 15, z = idx >> 7;
        const float* W = (z == 0) ? x : (z == 1) ? Wk : Wq;
        const float* v = (z == 0) ? nullptr : (z == 1) ? bq : bk;
        const int R = (z == 0) ? N_TOK : D_DIM;
        const int chunk = R / 16;
        const int d = dblk * 256 + tid;
        float s = 0.0f;
        for (int r = c * chunk; r < (c + 1) * chunk; ++r)
            s = fmaf(v ? v[r] : 1.0f, W[(size_t)r * D_DIM + d], s);
        g_part[(size_t)(z * 16 + c) * D_DIM + d] = s;
        vdone(g_vcnt + 0);
    } else if (idx < 408) {
        vwait(g_vcnt + 0, 384);
        int i2 = idx - 384, dblk = i2 & 7, z = i2 >> 3;
        const int d = dblk * 256 + tid;
        float s = 0.0f;
        #pragma unroll
        for (int c = 0; c < 16; ++c) s += g_part[(size_t)(z * 16 + c) * D_DIM + d];
        if (z == 0) g_u[d] = s;
        else if (z == 1) g_w1[d] = s;
        else g_v2[d] = s * sscale;
        vdone(g_vcnt + 1);
    } else if (idx < 666) {
        vwait(g_vcnt + 1, 24);
        int i2 = idx - 408;
        if (i2 < 256) {
            const int lane = tid & 31, w = tid >> 5;
            const float* W; const float* v; float* outv; int rbase; bool addb = false;
            if (i2 < 128)      { W = x;  v = g_w1; outv = g_t;  rbase = i2 * 32; }
            else if (i2 < 192) { W = Wk; v = g_u;  outv = g_y;  rbase = (i2 - 128) * 32; }
            else               { W = Wv; v = g_u;  outv = g_v3; rbase = (i2 - 192) * 32; addb = true; }
            for (int rr = 0; rr < 4; ++rr) {
                const int i = rbase + w * 4 + rr;
                float s = 0.0f;
                for (int j = lane; j < D_DIM; j += 32)
                    s = fmaf(W[(size_t)i * D_DIM + j], v[j], s);
                #pragma unroll
                for (int o = 16; o; o >>= 1) s += __shfl_xor_sync(0xFFFFFFFFu, s, o);
                if (lane == 0) outv[i] = addb ? s + (float)N_TOK * bv[i] : s;
            }
        } else {
            __shared__ float red[256];
            float s = 0.0f;
            if (i2 == 256) for (int i = tid; i < D_DIM; i += 256) s = fmaf(g_u[i], g_w1[i], s);
            else           for (int i = tid; i < D_DIM; i += 256) s = fmaf(bk[i], bq[i], s);
            red[tid] = s;
            __syncthreads();
            for (int o = 128; o; o >>= 1) { if (tid < o) red[tid] += red[tid + o]; __syncthreads(); }
            if (tid == 0) g_sc[i2 - 256] = red[0];
        }
        vdone(g_vcnt + 2);
    } else if (idx < 922) {
        vwait(g_vcnt + 2, 258);
        int i2 = idx - 666, dblk = i2 & 7, c = (i2 >> 3) & 15, z = i2 >> 7;
        const float* W = z ? Wq : x;
        const float* v = z ? g_y : g_t;
        const int R = z ? D_DIM : N_TOK;
        const int chunk = R / 16;
        const int d = dblk * 256 + tid;
        float s = 0.0f;
        for (int r = c * chunk; r < (c + 1) * chunk; ++r)
            s = fmaf(v[r], W[(size_t)r * D_DIM + d], s);
        g_part[(size_t)(z * 16 + c) * D_DIM + d] = s;
        vdone(g_vcnt + 3);
    } else if (idx < 938) {
        vwait(g_vcnt + 3, 256);
        int i2 = idx - 922, dblk = i2 & 7, z = i2 >> 3;
        const int d = dblk * 256 + tid;
        float s = 0.0f;
        #pragma unroll
        for (int c = 0; c < 16; ++c) s += g_part[(size_t)(z * 16 + c) * D_DIM + d];
        if (z == 0) g_w2[d] = s;
        else g_v1[d] = s * sscale;
        vdone(g_vcnt + 4);
    } else {
        vwait(g_vcnt + 4, 16);
        int i2 = idx - 938;
        const int lane = tid & 31, w = tid >> 5;
        for (int rr = 0; rr < 4; ++rr) {
            const int i = i2 * 32 + w * 4 + rr;
            float acc = 0.0f;
            for (int j = lane; j < D_DIM; j += 32)
                acc = fmaf(Wv[(size_t)i * D_DIM + j], g_w2[j], acc);
            #pragma unroll
            for (int o = 16; o; o >>= 1) acc += __shfl_xor_sync(0xFFFFFFFFu, acc, o);
            if (lane == 0) g_r[i] = sscale * (acc + bv[i] * g_sc[0] + g_v3[i] * g_sc[1]);
        }
        vdone(g_vcnt + 5);
    }
}

// ---------------- MEGA: 5 GEMMs + vec chain, one launch ----------------
// [0,136)      G  = xT xT^T (sym)                 -> flags [0,256)
// [136,392)    T1 = Wq^T Wk                       -> flags [256,512)
// [392,1394)   vec chain (counters)
// [1394,1650)  T2 = T1 G    waits T1 row + G row  -> flags [512,768)
// [1650,1906)  P  = s T2 Wv^T + rank2 (trans)     waits T2 row + vecE -> flags [768,1024)
// [1906,2930)  out = x P + 1 r^T (fp32, 64-row tiles) waits P(kb,j) + vecF
__global__ void __launch_bounds__(256, 2) mega(
    const float* __restrict__ x, const float* __restrict__ Wq, const float* __restrict__ bq,
    const float* __restrict__ Wk, const float* __restrict__ bk,
    const float* __restrict__ Wv, const float* __restrict__ bv,
    const __half* __restrict__ xTh,
    __half* __restrict__ gh,
    const __half* __restrict__ wqTh, const __half* __restrict__ wkTh,
    __half* __restrict__ t1h, __half* __restrict__ t2h,
    const __half* __restrict__ wvh,
    __half* __restrict__ pTh,
    const float* v1, const float* v2, const float* v3,
    const __half* __restrict__ xh,
    float* __restrict__ outp, const float* r, float s)
{
    extern __shared__ char dyn[];
    const int bid = blockIdx.x;

    if (bid < 136) {                        // G (symmetric)
        int idx = bid, by = 0;
        while (idx >= 16 - by) { idx -= 16 - by; ++by; }
        int bx = by + idx;
        gemm_body<4>(xTh, xTh, gh, nullptr,
                     nullptr, nullptr, nullptr, nullptr, nullptr,
                     by * 128, bx * 128, D_DIM, D_DIM, N_TOK, 1.0f, 1,
                     nullptr, nullptr, 1, dyn);
        set_flags(by * 16 + bx, bx * 16 + by);
    } else if (bid < 392) {                 // T1
        int idx = bid - 136;
        gemm_body<4>(wqTh, wkTh, t1h, nullptr,
                     nullptr, nullptr, nullptr, nullptr, nullptr,
                     (idx >> 4) * 128, (idx & 15) * 128, D_DIM, D_DIM, D_DIM, 1.0f, 0,
                     nullptr, nullptr, 1, dyn);
        set_flags(256 + idx, -1);
    } else if (bid < 1394) {                // vec chain
        vec_work(bid - 392, x, Wq, bq, Wk, bk, Wv, bv, s);
    } else if (bid < 1650) {                // T2 = T1 G
        int idx = bid - 1394;
        int m = idx >> 4, n = idx & 15;
        gemm_body<4>(t1h, gh, t2h, nullptr,
                     nullptr, nullptr, nullptr, nullptr, nullptr,
                     m * 128, n * 128, D_DIM, D_DIM, D_DIM, 1.0f, 0,
                     g_flags + 256 + m * 16, g_flags + n * 16, 1, dyn);
        set_flags(512 + idx, -1);
    } else if (bid < 1906) {                // P (trans + rank2)
        int idx = bid - 1650;
        int a = idx >> 4, j = idx & 15;
        vwait(g_vcnt + 4, 16);              // v1/v2/v3 ready
        gemm_body<4>(t2h, wvh, pTh, nullptr,
                     v1, bv, v2, v3, nullptr,
                     a * 128, j * 128, D_DIM, D_DIM, D_DIM, s, 2,
                     nullptr, g_flags + 512 + a * 16, 1, dyn);
        set_flags(768 + idx, -1);
    } else {                                // out (fp32, 64-row tiles)
        int idx = bid - 1906;               // 0..1023
        int t = idx >> 4, j = idx & 15;     // t: 0..63
        vwait(g_vcnt + 5, 64);              // r ready
        gemm_body<2>(xh, pTh, nullptr, outp,
                     nullptr, nullptr, nullptr, nullptr, r,
                     t * 64, j * 128, N_TOK, D_DIM, D_DIM, 1.0f, 3,
                     nullptr, g_flags + 768 + j, 16, dyn);
    }
}

// ---------------- preprocessing (one launch; bid 0 also zeroes flags) ----------------
__global__ void prep_all(const float* __restrict__ x,
                         __half* __restrict__ xh, __half* __restrict__ xth,
                         const float* __restrict__ Wq, __half* __restrict__ wqTh,
                         const float* __restrict__ Wk, __half* __restrict__ wkTh,
                         const float* __restrict__ Wv, __half* __restrict__ wvh)
{
    __shared__ float t[32][33];
    const int tx = threadIdx.x, ty = threadIdx.y;  // 32 x 8
    const int bid = blockIdx.x;
    const int tid = ty * 32 + tx;
    if (bid == 0) {
        for (int i = tid; i < 1024; i += 256) g_flags[i] = 0;
        if (tid < 8) g_vcnt[tid] = 0;
    }
    if (bid < 8192) {                       // x: straight hi + transposed hi
        int bx = (bid & 63) * 32, by = (bid >> 6) * 32;
        #pragma unroll
        for (int j = 0; j < 32; j += 8) {
            size_t gi = (size_t)(by + ty + j) * D_DIM + bx + tx;
            float v = x[gi];
            t[ty + j][tx] = v;
            xh[gi] = __float2half(v);
        }
        __syncthreads();
        #pragma unroll
        for (int j = 0; j < 32; j += 8) {
            size_t o = (size_t)(bx + ty + j) * N_TOK + by + tx;
            xth[o] = __float2half(t[tx][ty + j]);
        }
        return;
    }
    const int w = bid - 8192;
    const int z = w >> 12;
    const int rem = w & 4095;
    const int bx = (rem & 63) * 32, by = (rem >> 6) * 32;
    const float* in = (z == 0) ? Wq : (z == 1) ? Wk : Wv;
    if (z == 2) {                           // Wv: straight hi
        #pragma unroll
        for (int j = 0; j < 32; j += 8) {
            size_t gi = (size_t)(by + ty + j) * D_DIM + bx + tx;
            wvh[gi] = __float2half(in[gi]);
        }
        return;
    }
    __half* hi = (z == 0) ? wqTh : wkTh;    // transposed hi
    #pragma unroll
    for (int j = 0; j < 32; j += 8)
        t[ty + j][tx] = in[(size_t)(by + ty + j) * D_DIM + bx + tx];
    __syncthreads();
    #pragma unroll
    for (int j = 0; j < 32; j += 8) {
        size_t o = (size_t)(bx + ty + j) * D_DIM + by + tx;
        hi[o] = __float2half(t[tx][ty + j]);
    }
}

// ---------------- launcher ----------------
extern "C" void kernel_launch(void* const* d_in, const int* in_sizes, int n_in,
                              void* d_out, int out_size)
{
    const float* x  = (const float*)d_in[0];
    const float* Wq = (const float*)d_in[1];
    const float* bq = (const float*)d_in[2];
    const float* Wk = (const float*)d_in[3];
    const float* bk = (const float*)d_in[4];
    const float* Wv = (const float*)d_in[5];
    const float* bv = (const float*)d_in[6];
    float* out = (float*)d_out;

    __half *xT_hi, *x_hi, *wqT_hi, *wkT_hi, *wv_hi, *gh, *t1h, *t2h, *pTh;
    float *v1, *v2, *v3, *r;
    cudaGetSymbolAddress((void**)&xT_hi, g_xT_hi);
    cudaGetSymbolAddress((void**)&x_hi, g_x_hi);
    cudaGetSymbolAddress((void**)&wqT_hi, g_wqT_hi);
    cudaGetSymbolAddress((void**)&wkT_hi, g_wkT_hi);
    cudaGetSymbolAddress((void**)&wv_hi, g_wv_hi);
    cudaGetSymbolAddress((void**)&gh, g_g_hi);
    cudaGetSymbolAddress((void**)&t1h, g_t1_hi);
    cudaGetSymbolAddress((void**)&t2h, g_t2_hi);
    cudaGetSymbolAddress((void**)&pTh, g_pT_hi);
    cudaGetSymbolAddress((void**)&v1, g_v1);  cudaGetSymbolAddress((void**)&v2, g_v2);
    cudaGetSymbolAddress((void**)&v3, g_v3);  cudaGetSymbolAddress((void**)&r, g_r);

    cudaFuncSetAttribute(mega, cudaFuncAttributeMaxDynamicSharedMemorySize, SMEM_DYN);

    const float s = 1.0f / sqrtf((float)D_DIM);

    // prep (bid 0 zeroes flags/counters)
    prep_all<<<8192 + 3 * 4096, dim3(32, 8)>>>(x, x_hi, xT_hi,
                                               Wq, wqT_hi,
                                               Wk, wkT_hi,
                                               Wv, wv_hi);
    // everything else in one DAG launch
    mega<<<2930, 256, SMEM_DYN>>>(x, Wq, bq, Wk, bk, Wv, bv,
                                  xT_hi, gh,
                                  wqT_hi, wkT_hi,
                                  t1h, t2h,
                                  wv_hi, pTh,
                                  v1, v2, v3,
                                  x_hi, out, r, s);
}

// round 16
// speedup vs baseline: 1.0662x; 1.0662x over previous
#include <cuda_runtime.h>
#include <cuda_fp16.h>
#include <math.h>
#include <stdint.h>

#define D_DIM 2048
#define N_TOK 4096

// ---------------- device scratch (allocation-free rule) ----------------
__device__ __align__(128) __half g_xT_hi[(size_t)D_DIM * N_TOK];
__device__ __align__(128) __half g_x_hi [(size_t)N_TOK * D_DIM];
__device__ __align__(128) __half g_wqT_hi[(size_t)D_DIM * D_DIM];
__device__ __align__(128) __half g_wkT_hi[(size_t)D_DIM * D_DIM];
__device__ __align__(128) __half g_wv_hi[(size_t)D_DIM * D_DIM];
__device__ __align__(128) __half g_g_hi [(size_t)D_DIM * D_DIM];
__device__ __align__(128) __half g_t1_hi[(size_t)D_DIM * D_DIM];
__device__ __align__(128) __half g_t2_hi[(size_t)D_DIM * D_DIM];
__device__ __align__(128) __half g_pT_hi[(size_t)D_DIM * D_DIM];
__device__ float g_part[48 * D_DIM];
__device__ float g_u[D_DIM], g_w1[D_DIM], g_w2[D_DIM];
__device__ float g_v1[D_DIM], g_v2[D_DIM], g_v3[D_DIM], g_r[D_DIM];
__device__ float g_t[N_TOK], g_y[D_DIM];
__device__ float g_sc[2];
// tile flags: [0,256) G, [256,512) T1, [512,768) T2, [768,1024) P
__device__ int g_flags[1024];
// vec-stage counters: 0:A 1:B 2:C 3:D 4:E 5:F
__device__ int g_vcnt[8];

// ---------------- helpers ----------------
__device__ __forceinline__ uint32_t s2u(const void* p) {
    uint32_t a;
    asm("{ .reg .u64 t; cvta.to.shared.u64 t, %1; cvt.u32.u64 %0, t; }" : "=r"(a) : "l"(p));
    return a;
}
__device__ __forceinline__ void cp16(uint32_t dst, const void* src) {
    asm volatile("cp.async.cg.shared.global [%0], [%1], 16;" :: "r"(dst), "l"(src) : "memory");
}
__device__ __forceinline__ void cp_commit() {
    asm volatile("cp.async.commit_group;" ::: "memory");
}
template<int N>
__device__ __forceinline__ void cp_wait() {
    asm volatile("cp.async.wait_group %0;" :: "n"(N) : "memory");
}
__device__ __forceinline__ void ldsm4(uint32_t* r, uint32_t addr) {
    asm volatile("ldmatrix.sync.aligned.m8n8.x4.shared.b16 {%0,%1,%2,%3}, [%4];"
                 : "=r"(r[0]), "=r"(r[1]), "=r"(r[2]), "=r"(r[3]) : "r"(addr));
}
__device__ __forceinline__ void mma16816(float* d, const uint32_t* a, uint32_t b0, uint32_t b1) {
    asm volatile(
        "mma.sync.aligned.m16n8k16.row.col.f32.f16.f16.f32 "
        "{%0,%1,%2,%3}, {%4,%5,%6,%7}, {%8,%9}, {%0,%1,%2,%3};"
        : "+f"(d[0]), "+f"(d[1]), "+f"(d[2]), "+f"(d[3])
        : "r"(a[0]), "r"(a[1]), "r"(a[2]), "r"(a[3]), "r"(b0), "r"(b1));
}
__device__ __forceinline__ void wait_kblk(volatile int* wA, volatile int* wB, int sB,
                                          int kb, int tid) {
    if (tid == 0) {
        if (wA) while (wA[kb] == 0) __nanosleep(128);
        while (wB[kb * sB] == 0) __nanosleep(128);
        __threadfence();
    }
    __syncthreads();
}
__device__ __forceinline__ void vwait(volatile int* cnt, int target) {
    if (threadIdx.x == 0) {
        while (*cnt < target) __nanosleep(256);
        __threadfence();
    }
    __syncthreads();
}
__device__ __forceinline__ void vdone(int* cnt) {
    __threadfence();
    __syncthreads();
    if (threadIdx.x == 0) atomicAdd(cnt, 1);
}

// ---------------- pure fp16 HMMA GEMM body (single pass, BK=64) ----------------
// C[m,n] = alpha * sum_k Ah[m,k] * Bh[n,k]
// mode 0 NORM / 1 SYM / 2 TRANS+rank2 / 3 FINAL fp32
// wB != null => progressive waits per 128-wide K-block (every 2nd chunk).
#define PLANE_B 18432              // 128 rows x 144 B (128 data + 16 pad)
#define STAGE_B 36864
static const int SMEM_DYN = 2 * STAGE_B;

__device__ __forceinline__ void gemm_body(
    const __half* __restrict__ Ah, const __half* __restrict__ Bh,
    __half* Ch, float* Cf,
    const float* cA, const float* cB, const float* cC, const float* cD,
    const float* biascol,
    int bm0, int bn0, int Mtot, int Ntot, int Kd, float alpha, int mode,
    volatile int* wA, volatile int* wB, int sB,
    char* dyn)
{
    const uint32_t su = s2u(dyn);
    const int tid  = threadIdx.x;
    const int wid  = tid >> 5, lane = tid & 31;
    const int wm0  = (wid & 1) * 64;
    const int wn0  = (wid >> 1) * 32;

    // cp.async: 2048 16B transfers / 256 threads = 8 each (plane 0:A, 1:B)
    const __half* gsrc[8];
    uint32_t doff[8];
    #pragma unroll
    for (int i = 0; i < 8; ++i) {
        int idx   = i * 256 + tid;
        int plane = idx >> 10;
        int row   = (idx >> 3) & 127;
        int seg   = idx & 7;
        const __half* base = (plane == 0) ? Ah : Bh;
        int grow = (plane == 0 ? bm0 : bn0) + row;
        gsrc[i] = base + (size_t)grow * Kd + seg * 8;
        doff[i] = (uint32_t)(plane * PLANE_B + row * 144 + seg * 16);
    }

    const int NC = Kd / 64;
    if (wB) wait_kblk(wA, wB, sB, 0, tid);
    #pragma unroll
    for (int i = 0; i < 8; ++i) cp16(su + doff[i], gsrc[i]);
    cp_commit();

    float acc[4][4][4];
    #pragma unroll
    for (int im = 0; im < 4; ++im)
        #pragma unroll
        for (int in = 0; in < 4; ++in)
            #pragma unroll
            for (int j = 0; j < 4; ++j) acc[im][in][j] = 0.0f;

    const int a_rl = ((lane >> 3) & 1) * 8 + (lane & 7);
    const int a_ch = ((lane >> 4) & 1) * 16;
    const int b_rl = lane;

    for (int c = 0; c < NC; ++c) {
        cp_wait<0>();
        __syncthreads();
        if (c + 1 < NC) {
            if (wB && (((c + 1) & 1) == 0))
                wait_kblk(wA, wB, sB, (c + 1) >> 1, tid);
            const uint32_t sd = su + ((c + 1) & 1) * STAGE_B;
            const size_t koff = (size_t)(c + 1) * 64;
            #pragma unroll
            for (int i = 0; i < 8; ++i) cp16(sd + doff[i], gsrc[i] + koff);
            cp_commit();
        }
        const uint32_t sb = su + (c & 1) * STAGE_B;
        const uint32_t aBase = sb + (wm0 + a_rl) * 144 + a_ch;
        const uint32_t bBase = sb + (wn0 + b_rl) * 144 + PLANE_B;

        #pragma unroll
        for (int kk = 0; kk < 4; ++kk) {
            const uint32_t kO = kk * 32;
            uint32_t a[4][4], b0[4], b1[4];
            ldsm4(b0, bBase + kO);
            ldsm4(b1, bBase + kO + 16);
            #pragma unroll
            for (int im = 0; im < 4; ++im)
                ldsm4(a[im], aBase + im * (16 * 144) + kO);
            #pragma unroll
            for (int im = 0; im < 4; ++im)
                #pragma unroll
                for (int in = 0; in < 4; ++in)
                    mma16816(acc[im][in], a[im], b0[in], b1[in]);
        }
    }

    // ---- epilogue ----
    const int mbase = bm0 + wm0 + (lane >> 2);
    const int nbase = bn0 + wn0 + (lane & 3) * 2;
    #pragma unroll
    for (int im = 0; im < 4; ++im) {
        #pragma unroll
        for (int in = 0; in < 4; ++in) {
            const float* d = acc[im][in];
            const int n0 = nbase + in * 8;
            const int m0 = mbase + im * 16;
            if (mode == 3) {
                float2 v0, v1;
                v0.x = d[0] * alpha + biascol[n0];
                v0.y = d[1] * alpha + biascol[n0 + 1];
                v1.x = d[2] * alpha + biascol[n0];
                v1.y = d[3] * alpha + biascol[n0 + 1];
                *(float2*)(Cf + (size_t)m0 * Ntot + n0)       = v0;
                *(float2*)(Cf + (size_t)(m0 + 8) * Ntot + n0) = v1;
            } else if (mode == 0 || mode == 1) {
                // packed half2 row-major stores (n0, n0+1 adjacent)
                __half2 h01 = __floats2half2_rn(d[0] * alpha, d[1] * alpha);
                __half2 h23 = __floats2half2_rn(d[2] * alpha, d[3] * alpha);
                *(__half2*)(Ch + (size_t)m0 * Ntot + n0)       = h01;
                *(__half2*)(Ch + (size_t)(m0 + 8) * Ntot + n0) = h23;
                if (mode == 1) {  // mirror (column scatter, scalar)
                    Ch[(size_t)n0 * Ntot + m0]           = __low2half(h01);
                    Ch[(size_t)(n0 + 1) * Ntot + m0]     = __high2half(h01);
                    Ch[(size_t)n0 * Ntot + m0 + 8]       = __low2half(h23);
                    Ch[(size_t)(n0 + 1) * Ntot + m0 + 8] = __high2half(h23);
                }
            } else {              // mode 2: trans store + rank2 (column scatter)
                #pragma unroll
                for (int j = 0; j < 4; ++j) {
                    const int m = m0 + (j >> 1) * 8;
                    const int n = n0 + (j & 1);
                    float v = d[j] * alpha + cA[m] * cB[n] + cC[m] * cD[n];
                    Ch[(size_t)n * Mtot + m] = __float2half(v);
                }
            }
        }
    }
}

__device__ __forceinline__ void set_flags(int f0, int f1) {
    __threadfence();
    __syncthreads();
    if (threadIdx.x == 0) {
        atomicExch(g_flags + f0, 1);
        if (f1 >= 0) atomicExch(g_flags + f1, 1);
    }
}

// ---------------- vec chain inside mega: idx in [0,1002) ----------------
__device__ void vec_work(int idx,
                         const float* x, const float* Wq, const float* bq,
                         const float* Wk, const float* bk,
                         const float* Wv, const float* bv, float sscale)
{
    const int tid = threadIdx.x;
    if (idx < 384) {
        int dblk = idx & 7, c = (idx >> 3) & 15, z = idx >> 7;
        const float* W = (z == 0) ? x : (z == 1) ? Wk : Wq;
        const float* v = (z == 0) ? nullptr : (z == 1) ? bq : bk;
        const int R = (z == 0) ? N_TOK : D_DIM;
        const int chunk = R / 16;
        const int d = dblk * 256 + tid;
        float s = 0.0f;
        for (int r = c * chunk; r < (c + 1) * chunk; ++r)
            s = fmaf(v ? v[r] : 1.0f, W[(size_t)r * D_DIM + d], s);
        g_part[(size_t)(z * 16 + c) * D_DIM + d] = s;
        vdone(g_vcnt + 0);
    } else if (idx < 408) {
        vwait(g_vcnt + 0, 384);
        int i2 = idx - 384, dblk = i2 & 7, z = i2 >> 3;
        const int d = dblk * 256 + tid;
        float s = 0.0f;
        #pragma unroll
        for (int c = 0; c < 16; ++c) s += g_part[(size_t)(z * 16 + c) * D_DIM + d];
        if (z == 0) g_u[d] = s;
        else if (z == 1) g_w1[d] = s;
        else g_v2[d] = s * sscale;
        vdone(g_vcnt + 1);
    } else if (idx < 666) {
        vwait(g_vcnt + 1, 24);
        int i2 = idx - 408;
        if (i2 < 256) {
            const int lane = tid & 31, w = tid >> 5;
            const float* W; const float* v; float* outv; int rbase; bool addb = false;
            if (i2 < 128)      { W = x;  v = g_w1; outv = g_t;  rbase = i2 * 32; }
            else if (i2 < 192) { W = Wk; v = g_u;  outv = g_y;  rbase = (i2 - 128) * 32; }
            else               { W = Wv; v = g_u;  outv = g_v3; rbase = (i2 - 192) * 32; addb = true; }
            for (int rr = 0; rr < 4; ++rr) {
                const int i = rbase + w * 4 + rr;
                float s = 0.0f;
                for (int j = lane; j < D_DIM; j += 32)
                    s = fmaf(W[(size_t)i * D_DIM + j], v[j], s);
                #pragma unroll
                for (int o = 16; o; o >>= 1) s += __shfl_xor_sync(0xFFFFFFFFu, s, o);
                if (lane == 0) outv[i] = addb ? s + (float)N_TOK * bv[i] : s;
            }
        } else {
            __shared__ float red[256];
            float s = 0.0f;
            if (i2 == 256) for (int i = tid; i < D_DIM; i += 256) s = fmaf(g_u[i], g_w1[i], s);
            else           for (int i = tid; i < D_DIM; i += 256) s = fmaf(bk[i], bq[i], s);
            red[tid] = s;
            __syncthreads();
            for (int o = 128; o; o >>= 1) { if (tid < o) red[tid] += red[tid + o]; __syncthreads(); }
            if (tid == 0) g_sc[i2 - 256] = red[0];
        }
        vdone(g_vcnt + 2);
    } else if (idx < 922) {
        vwait(g_vcnt + 2, 258);
        int i2 = idx - 666, dblk = i2 & 7, c = (i2 >> 3) & 15, z = i2 >> 7;
        const float* W = z ? Wq : x;
        const float* v = z ? g_y : g_t;
        const int R = z ? D_DIM : N_TOK;
        const int chunk = R / 16;
        const int d = dblk * 256 + tid;
        float s = 0.0f;
        for (int r = c * chunk; r < (c + 1) * chunk; ++r)
            s = fmaf(v[r], W[(size_t)r * D_DIM + d], s);
        g_part[(size_t)(z * 16 + c) * D_DIM + d] = s;
        vdone(g_vcnt + 3);
    } else if (idx < 938) {
        vwait(g_vcnt + 3, 256);
        int i2 = idx - 922, dblk = i2 & 7, z = i2 >> 3;
        const int d = dblk * 256 + tid;
        float s = 0.0f;
        #pragma unroll
        for (int c = 0; c < 16; ++c) s += g_part[(size_t)(z * 16 + c) * D_DIM + d];
        if (z == 0) g_w2[d] = s;
        else g_v1[d] = s * sscale;
        vdone(g_vcnt + 4);
    } else {
        vwait(g_vcnt + 4, 16);
        int i2 = idx - 938;
        const int lane = tid & 31, w = tid >> 5;
        for (int rr = 0; rr < 4; ++rr) {
            const int i = i2 * 32 + w * 4 + rr;
            float acc = 0.0f;
            for (int j = lane; j < D_DIM; j += 32)
                acc = fmaf(Wv[(size_t)i * D_DIM + j], g_w2[j], acc);
            #pragma unroll
            for (int o = 16; o; o >>= 1) acc += __shfl_xor_sync(0xFFFFFFFFu, acc, o);
            if (lane == 0) g_r[i] = sscale * (acc + bv[i] * g_sc[0] + g_v3[i] * g_sc[1]);
        }
        vdone(g_vcnt + 5);
    }
}

// ---------------- MEGA: 5 GEMMs + vec chain, one launch ----------------
// [0,136)      G  = xT xT^T (sym)                 -> flags [0,256)
// [136,392)    T1 = Wq^T Wk                       -> flags [256,512)
// [392,1394)   vec chain (counters)
// [1394,1650)  T2 = T1 G    waits T1 row + G row  -> flags [512,768)
// [1650,1906)  P  = s T2 Wv^T + rank2 (trans)     waits T2 row + vecE -> flags [768,1024)
// [1906,2418)  out = x P + 1 r^T (fp32)           waits P(kb,j) + vecF
__global__ void __launch_bounds__(256, 2) mega(
    const float* __restrict__ x, const float* __restrict__ Wq, const float* __restrict__ bq,
    const float* __restrict__ Wk, const float* __restrict__ bk,
    const float* __restrict__ Wv, const float* __restrict__ bv,
    const __half* __restrict__ xTh,
    __half* __restrict__ gh,
    const __half* __restrict__ wqTh, const __half* __restrict__ wkTh,
    __half* __restrict__ t1h, __half* __restrict__ t2h,
    const __half* __restrict__ wvh,
    __half* __restrict__ pTh,
    const float* v1, const float* v2, const float* v3,
    const __half* __restrict__ xh,
    float* __restrict__ outp, const float* r, float s)
{
    extern __shared__ char dyn[];
    const int bid = blockIdx.x;

    if (bid < 136) {                        // G (symmetric)
        int idx = bid, by = 0;
        while (idx >= 16 - by) { idx -= 16 - by; ++by; }
        int bx = by + idx;
        gemm_body(xTh, xTh, gh, nullptr,
                  nullptr, nullptr, nullptr, nullptr, nullptr,
                  by * 128, bx * 128, D_DIM, D_DIM, N_TOK, 1.0f, 1,
                  nullptr, nullptr, 1, dyn);
        set_flags(by * 16 + bx, bx * 16 + by);
    } else if (bid < 392) {                 // T1
        int idx = bid - 136;
        gemm_body(wqTh, wkTh, t1h, nullptr,
                  nullptr, nullptr, nullptr, nullptr, nullptr,
                  (idx >> 4) * 128, (idx & 15) * 128, D_DIM, D_DIM, D_DIM, 1.0f, 0,
                  nullptr, nullptr, 1, dyn);
        set_flags(256 + idx, -1);
    } else if (bid < 1394) {                // vec chain
        vec_work(bid - 392, x, Wq, bq, Wk, bk, Wv, bv, s);
    } else if (bid < 1650) {                // T2 = T1 G
        int idx = bid - 1394;
        int m = idx >> 4, n = idx & 15;
        gemm_body(t1h, gh, t2h, nullptr,
                  nullptr, nullptr, nullptr, nullptr, nullptr,
                  m * 128, n * 128, D_DIM, D_DIM, D_DIM, 1.0f, 0,
                  g_flags + 256 + m * 16, g_flags + n * 16, 1, dyn);
        set_flags(512 + idx, -1);
    } else if (bid < 1906) {                // P (trans + rank2)
        int idx = bid - 1650;
        int a = idx >> 4, j = idx & 15;
        vwait(g_vcnt + 4, 16);              // v1/v2/v3 ready
        gemm_body(t2h, wvh, pTh, nullptr,
                  v1, bv, v2, v3, nullptr,
                  a * 128, j * 128, D_DIM, D_DIM, D_DIM, s, 2,
                  nullptr, g_flags + 512 + a * 16, 1, dyn);
        set_flags(768 + idx, -1);
    } else {                                // out (fp32)
        int idx = bid - 1906;
        int t = idx >> 4, j = idx & 15;
        vwait(g_vcnt + 5, 64);              // r ready
        gemm_body(xh, pTh, nullptr, outp,
                  nullptr, nullptr, nullptr, nullptr, r,
                  t * 128, j * 128, N_TOK, D_DIM, D_DIM, 1.0f, 3,
                  nullptr, g_flags + 768 + j, 16, dyn);
    }
}

// ---------------- preprocessing (one launch; bid 0 also zeroes flags) ----------------
__global__ void prep_all(const float* __restrict__ x,
                         __half* __restrict__ xh, __half* __restrict__ xth,
                         const float* __restrict__ Wq, __half* __restrict__ wqTh,
                         const float* __restrict__ Wk, __half* __restrict__ wkTh,
                         const float* __restrict__ Wv, __half* __restrict__ wvh)
{
    __shared__ float t[32][33];
    const int tx = threadIdx.x, ty = threadIdx.y;  // 32 x 8
    const int bid = blockIdx.x;
    const int tid = ty * 32 + tx;
    if (bid == 0) {
        for (int i = tid; i < 1024; i += 256) g_flags[i] = 0;
        if (tid < 8) g_vcnt[tid] = 0;
    }
    if (bid < 8192) {                       // x: straight hi + transposed hi
        int bx = (bid & 63) * 32, by = (bid >> 6) * 32;
        #pragma unroll
        for (int j = 0; j < 32; j += 8) {
            size_t gi = (size_t)(by + ty + j) * D_DIM + bx + tx;
            float v = x[gi];
            t[ty + j][tx] = v;
            xh[gi] = __float2half(v);
        }
        __syncthreads();
        #pragma unroll
        for (int j = 0; j < 32; j += 8) {
            size_t o = (size_t)(bx + ty + j) * N_TOK + by + tx;
            xth[o] = __float2half(t[tx][ty + j]);
        }
        return;
    }
    const int w = bid - 8192;
    const int z = w >> 12;
    const int rem = w & 4095;
    const int bx = (rem & 63) * 32, by = (rem >> 6) * 32;
    const float* in = (z == 0) ? Wq : (z == 1) ? Wk : Wv;
    if (z == 2) {                           // Wv: straight hi
        #pragma unroll
        for (int j = 0; j < 32; j += 8) {
            size_t gi = (size_t)(by + ty + j) * D_DIM + bx + tx;
            wvh[gi] = __float2half(in[gi]);
        }
        return;
    }
    __half* hi = (z == 0) ? wqTh : wkTh;    // transposed hi
    #pragma unroll
    for (int j = 0; j < 32; j += 8)
        t[ty + j][tx] = in[(size_t)(by + ty + j) * D_DIM + bx + tx];
    __syncthreads();
    #pragma unroll
    for (int j = 0; j < 32; j += 8) {
        size_t o = (size_t)(bx + ty + j) * D_DIM + by + tx;
        hi[o] = __float2half(t[tx][ty + j]);
    }
}

// ---------------- launcher ----------------
extern "C" void kernel_launch(void* const* d_in, const int* in_sizes, int n_in,
                              void* d_out, int out_size)
{
    const float* x  = (const float*)d_in[0];
    const float* Wq = (const float*)d_in[1];
    const float* bq = (const float*)d_in[2];
    const float* Wk = (const float*)d_in[3];
    const float* bk = (const float*)d_in[4];
    const float* Wv = (const float*)d_in[5];
    const float* bv = (const float*)d_in[6];
    float* out = (float*)d_out;

    __half *xT_hi, *x_hi, *wqT_hi, *wkT_hi, *wv_hi, *gh, *t1h, *t2h, *pTh;
    float *v1, *v2, *v3, *r;
    cudaGetSymbolAddress((void**)&xT_hi, g_xT_hi);
    cudaGetSymbolAddress((void**)&x_hi, g_x_hi);
    cudaGetSymbolAddress((void**)&wqT_hi, g_wqT_hi);
    cudaGetSymbolAddress((void**)&wkT_hi, g_wkT_hi);
    cudaGetSymbolAddress((void**)&wv_hi, g_wv_hi);
    cudaGetSymbolAddress((void**)&gh, g_g_hi);
    cudaGetSymbolAddress((void**)&t1h, g_t1_hi);
    cudaGetSymbolAddress((void**)&t2h, g_t2_hi);
    cudaGetSymbolAddress((void**)&pTh, g_pT_hi);
    cudaGetSymbolAddress((void**)&v1, g_v1);  cudaGetSymbolAddress((void**)&v2, g_v2);
    cudaGetSymbolAddress((void**)&v3, g_v3);  cudaGetSymbolAddress((void**)&r, g_r);

    cudaFuncSetAttribute(mega, cudaFuncAttributeMaxDynamicSharedMemorySize, SMEM_DYN);

    const float s = 1.0f / sqrtf((float)D_DIM);

    // prep (bid 0 zeroes flags/counters)
    prep_all<<<8192 + 3 * 4096, dim3(32, 8)>>>(x, x_hi, xT_hi,
                                               Wq, wqT_hi,
                                               Wk, wkT_hi,
                                               Wv, wv_hi);
    // everything else in one DAG launch
    mega<<<2418, 256, SMEM_DYN>>>(x, Wq, bq, Wk, bk, Wv, bv,
                                  xT_hi, gh,
                                  wqT_hi, wkT_hi,
                                  t1h, t2h,
                                  wv_hi, pTh,
                                  v1, v2, v3,
                                  x_hi, out, r, s);
}